// round 9
// baseline (speedup 1.0000x reference)
#include <cuda_runtime.h>
#include <cuda_fp16.h>
#include <cuda_bf16.h>

#define NMAX 100000
#define EMAX 1600000

// ---- device scratch (no allocations allowed) ----
static __device__ __half g_xh_h[NMAX * 128];   // projected features fp16 [N,128]
static __device__ float g_asrc[NMAX * 8];      // per-node src logits [N,H]
static __device__ float g_adst[NMAX * 8];      // per-node dst logits [N,H]
static __device__ int   g_cnt[NMAX];           // in-degree histogram
static __device__ int   g_off[NMAX + 1];       // CSR offsets
static __device__ int   g_blk[128];            // scan partials
static __device__ int   g_rank[EMAX];          // edge rank within dst segment
static __device__ int   g_sorted[EMAX];        // src ids grouped by dst

// ---------------------------------------------------------------------------
__global__ void zero_kernel(int n) {
    int i = blockIdx.x * blockDim.x + threadIdx.x;
    if (i < n) g_cnt[i] = 0;
}

// ---------------------------------------------------------------------------
__device__ __forceinline__ unsigned f2tf32(float f) {
    unsigned r;
    asm("cvt.rna.tf32.f32 %0, %1;" : "=r"(r) : "f"(f));
    return r;
}
__device__ __forceinline__ void mma_tf32(float* c,
    unsigned a0, unsigned a1, unsigned a2, unsigned a3,
    unsigned b0, unsigned b1)
{
    asm volatile(
        "mma.sync.aligned.m16n8k8.row.col.f32.tf32.tf32.f32 "
        "{%0,%1,%2,%3}, {%4,%5,%6,%7}, {%8,%9}, {%0,%1,%2,%3};"
        : "+f"(c[0]), "+f"(c[1]), "+f"(c[2]), "+f"(c[3])
        : "r"(a0), "r"(a1), "r"(a2), "r"(a3), "r"(b0), "r"(b1));
}

// xh = x @ W^T + b via tf32 mma; att logits fused into the epilogue.
__global__ __launch_bounds__(256, 2) void gemm_kernel(
    const float* __restrict__ x, const float* __restrict__ W,
    const float* __restrict__ b,
    const float* __restrict__ att_s, const float* __restrict__ att_d, int n)
{
    __shared__ unsigned ws[128 * 36];   // W[j][k] chunk, tf32 bits
    __shared__ unsigned xs[128 * 36];   // x[r][k] chunk, tf32 bits
    __shared__ float as_sm[128], ad_sm[128], b_sm[128];
    const int tid = threadIdx.x;
    const int lane = tid & 31, warp = tid >> 5;
    const int row0 = blockIdx.x * 128;
    const int g = lane >> 2;        // groupID (row selector)
    const int tg = lane & 3;        // thread-in-group (col selector)

    if (tid < 128) {
        as_sm[tid] = att_s[tid];
        ad_sm[tid] = att_d[tid];
        b_sm[tid]  = b[tid];
    }

    float acc[16][4];
#pragma unroll
    for (int t = 0; t < 16; t++)
#pragma unroll
        for (int c = 0; c < 4; c++) acc[t][c] = 0.f;

    for (int kk = 0; kk < 128; kk += 32) {
#pragma unroll
        for (int i = 0; i < 4; i++) {           // W chunk: 128x32
            int id = tid + i * 256;             // float4 index
            int j = id >> 3, kq = (id & 7) * 4;
            float4 v = *(const float4*)&W[j * 128 + kk + kq];
            unsigned* d = &ws[j * 36 + kq];
            d[0] = f2tf32(v.x); d[1] = f2tf32(v.y);
            d[2] = f2tf32(v.z); d[3] = f2tf32(v.w);
        }
#pragma unroll
        for (int i = 0; i < 4; i++) {           // x chunk: 128x32
            int id = tid + i * 256;
            int r = id >> 3, kq = (id & 7) * 4;
            int row = row0 + r;
            float4 v = (row < n) ? *(const float4*)&x[row * 128 + kk + kq]
                                 : make_float4(0.f, 0.f, 0.f, 0.f);
            unsigned* d = &xs[r * 36 + kq];
            d[0] = f2tf32(v.x); d[1] = f2tf32(v.y);
            d[2] = f2tf32(v.z); d[3] = f2tf32(v.w);
        }
        __syncthreads();
        const int rA = warp * 16 + g;
#pragma unroll
        for (int ks = 0; ks < 32; ks += 8) {
            unsigned a0 = xs[rA * 36 + ks + tg];
            unsigned a1 = xs[(rA + 8) * 36 + ks + tg];
            unsigned a2 = xs[rA * 36 + ks + 4 + tg];
            unsigned a3 = xs[(rA + 8) * 36 + ks + 4 + tg];
#pragma unroll
            for (int t = 0; t < 16; t++) {
                int jn = t * 8 + g;
                unsigned b0 = ws[jn * 36 + ks + tg];
                unsigned b1 = ws[jn * 36 + ks + 4 + tg];
                mma_tf32(acc[t], a0, a1, a2, a3, b0, b1);
            }
        }
        __syncthreads();
    }

    // epilogue: +bias, store fp16, fused per-head attention logits
    const int r0 = row0 + warp * 16 + g;
    const bool okA = (r0 < n), okB = (r0 + 8 < n);
#pragma unroll
    for (int h = 0; h < 8; h++) {
        float sA = 0.f, dA = 0.f, sB = 0.f, dB = 0.f;
#pragma unroll
        for (int tt = 0; tt < 2; tt++) {
            const int t  = 2 * h + tt;
            const int j0 = t * 8 + 2 * tg;
            float bx = b_sm[j0], by = b_sm[j0 + 1];
            float v00 = acc[t][0] + bx, v01 = acc[t][1] + by;
            float v10 = acc[t][2] + bx, v11 = acc[t][3] + by;
            if (okA) *(__half2*)&g_xh_h[r0 * 128 + j0] = __floats2half2_rn(v00, v01);
            if (okB) *(__half2*)&g_xh_h[(r0 + 8) * 128 + j0] = __floats2half2_rn(v10, v11);
            float a0 = as_sm[j0], a1 = as_sm[j0 + 1];
            float q0 = ad_sm[j0], q1 = ad_sm[j0 + 1];
            sA += v00 * a0 + v01 * a1;  dA += v00 * q0 + v01 * q1;
            sB += v10 * a0 + v11 * a1;  dB += v10 * q0 + v11 * q1;
        }
        sA += __shfl_xor_sync(0xffffffffu, sA, 1); sA += __shfl_xor_sync(0xffffffffu, sA, 2);
        dA += __shfl_xor_sync(0xffffffffu, dA, 1); dA += __shfl_xor_sync(0xffffffffu, dA, 2);
        sB += __shfl_xor_sync(0xffffffffu, sB, 1); sB += __shfl_xor_sync(0xffffffffu, sB, 2);
        dB += __shfl_xor_sync(0xffffffffu, dB, 1); dB += __shfl_xor_sync(0xffffffffu, dB, 2);
        if ((h & 3) == tg) {
            if (okA) { g_asrc[r0 * 8 + h] = sA; g_adst[r0 * 8 + h] = dA; }
            if (okB) { g_asrc[(r0 + 8) * 8 + h] = sB; g_adst[(r0 + 8) * 8 + h] = dB; }
        }
    }
}

// ---------------------------------------------------------------------------
// histogram + per-edge rank within destination segment
__global__ void hist4_kernel(const int* __restrict__ ei, int ne) {
    int i = blockIdx.x * blockDim.x + threadIdx.x;
    int ne4 = ne >> 2;
    if (i < ne4) {
        int4 d = ((const int4*)(ei + ne))[i];
        int4 r;
        r.x = atomicAdd(&g_cnt[d.x], 1);
        r.y = atomicAdd(&g_cnt[d.y], 1);
        r.z = atomicAdd(&g_cnt[d.z], 1);
        r.w = atomicAdd(&g_cnt[d.w], 1);
        ((int4*)g_rank)[i] = r;
    }
}
__global__ void hist_kernel(const int* __restrict__ ei, int ne) {
    int i = blockIdx.x * blockDim.x + threadIdx.x;
    if (i < ne) g_rank[i] = atomicAdd(&g_cnt[ei[ne + i]], 1);
}

// ---- scan: block sums, then per-block self-computed offset ----------------
__global__ void scan_a(int n) {
    __shared__ int sd[32];
    int t = threadIdx.x;
    int idx = blockIdx.x * 1024 + t;
    int v = (idx < n) ? g_cnt[idx] : 0;
#pragma unroll
    for (int d = 16; d; d >>= 1) v += __shfl_xor_sync(0xffffffffu, v, d);
    if ((t & 31) == 0) sd[t >> 5] = v;
    __syncthreads();
    if (t < 32) {
        int s = sd[t];
#pragma unroll
        for (int d = 16; d; d >>= 1) s += __shfl_xor_sync(0xffffffffu, s, d);
        if (t == 0) g_blk[blockIdx.x] = s;
    }
}
// Each block sums preceding g_blk partials itself (<=128 values), then local scan.
__global__ void scan_c(int n) {
    __shared__ int wsum[32];
    __shared__ int blockoff;
    int t = threadIdx.x;
    int idx = blockIdx.x * 1024 + t;
    int lane = t & 31, w = t >> 5;
    if (w == 0) {
        int s = 0;
        for (int j = lane; j < blockIdx.x; j += 32) s += g_blk[j];
#pragma unroll
        for (int d = 16; d; d >>= 1) s += __shfl_xor_sync(0xffffffffu, s, d);
        if (lane == 0) blockoff = s;
    }
    int v = (idx < n) ? g_cnt[idx] : 0;
    int inc = v;
#pragma unroll
    for (int d = 1; d < 32; d <<= 1) {
        int u = __shfl_up_sync(0xffffffffu, inc, d);
        if (lane >= d) inc += u;
    }
    if (lane == 31) wsum[w] = inc;
    __syncthreads();
    if (w == 0) {
        int s = (lane < 32) ? wsum[lane] : 0;
        int si = s;
#pragma unroll
        for (int d = 1; d < 32; d <<= 1) {
            int u = __shfl_up_sync(0xffffffffu, si, d);
            if (lane >= d) si += u;
        }
        wsum[lane] = si - s;   // exclusive offsets of warps
    }
    __syncthreads();
    int excl = (inc - v) + wsum[w] + blockoff;
    if (idx < n) g_off[idx] = excl;
    if (idx == n - 1) g_off[n] = excl + v;
}

// ---------------------------------------------------------------------------
// atomic-free scatter using precomputed ranks
__global__ void scat4_kernel(const int* __restrict__ ei, int ne) {
    int i = blockIdx.x * blockDim.x + threadIdx.x;
    int ne4 = ne >> 2;
    if (i < ne4) {
        int4 s = ((const int4*)ei)[i];
        int4 d = ((const int4*)(ei + ne))[i];
        int4 r = ((const int4*)g_rank)[i];
        g_sorted[g_off[d.x] + r.x] = s.x;
        g_sorted[g_off[d.y] + r.y] = s.y;
        g_sorted[g_off[d.z] + r.z] = s.z;
        g_sorted[g_off[d.w] + r.w] = s.w;
    }
}
__global__ void scat_kernel(const int* __restrict__ ei, int ne) {
    int i = blockIdx.x * blockDim.x + threadIdx.x;
    if (i < ne) {
        int d = ei[ne + i];
        g_sorted[g_off[d] + g_rank[i]] = ei[i];
    }
}

// ---------------------------------------------------------------------------
// Warp per destination node. Lane l owns dims [4l,4l+4) => head = l>>2.
// Softmax without max-subtraction (logits bounded):
//   out = (sum_e w_e * xh[src_e]) / (sum_e w_e),  w = exp(leakyrelu(asrc+adst))
__global__ void agg_kernel(const float* __restrict__ bias,
                           float* __restrict__ out, int n)
{
    int warp = (blockIdx.x * blockDim.x + threadIdx.x) >> 5;
    int lane = threadIdx.x & 31;
    if (warp >= n) return;
    int h = lane >> 2;
    float adst = g_adst[warp * 8 + h];

    // self loop
    float asl = g_asrc[warp * 8 + h];
    float lg = asl + adst;
    float wgt = __expf(lg > 0.f ? lg : 0.2f * lg);
    uint2 u = *(const uint2*)&g_xh_h[warp * 128 + lane * 4];
    float2 f0 = __half22float2(*reinterpret_cast<__half2*>(&u.x));
    float2 f1 = __half22float2(*reinterpret_cast<__half2*>(&u.y));
    float denom = wgt;
    float4 acc;
    acc.x = wgt * f0.x; acc.y = wgt * f0.y;
    acc.z = wgt * f1.x; acc.w = wgt * f1.y;

    const int e1 = g_off[warp + 1];
    int e = g_off[warp];
    for (; e + 3 < e1; e += 4) {
        int s0 = g_sorted[e],     s1 = g_sorted[e + 1];
        int s2 = g_sorted[e + 2], s3 = g_sorted[e + 3];
        float a0 = g_asrc[s0 * 8 + h], a1 = g_asrc[s1 * 8 + h];
        float a2 = g_asrc[s2 * 8 + h], a3 = g_asrc[s3 * 8 + h];
        uint2 v0 = *(const uint2*)&g_xh_h[s0 * 128 + lane * 4];
        uint2 v1 = *(const uint2*)&g_xh_h[s1 * 128 + lane * 4];
        uint2 v2 = *(const uint2*)&g_xh_h[s2 * 128 + lane * 4];
        uint2 v3 = *(const uint2*)&g_xh_h[s3 * 128 + lane * 4];
        float l0 = a0 + adst, l1 = a1 + adst, l2 = a2 + adst, l3 = a3 + adst;
        float w0 = __expf(l0 > 0.f ? l0 : 0.2f * l0);
        float w1 = __expf(l1 > 0.f ? l1 : 0.2f * l1);
        float w2 = __expf(l2 > 0.f ? l2 : 0.2f * l2);
        float w3 = __expf(l3 > 0.f ? l3 : 0.2f * l3);
        denom += w0 + w1 + w2 + w3;
        float2 p, q;
        p = __half22float2(*reinterpret_cast<__half2*>(&v0.x));
        q = __half22float2(*reinterpret_cast<__half2*>(&v0.y));
        acc.x += w0 * p.x; acc.y += w0 * p.y; acc.z += w0 * q.x; acc.w += w0 * q.y;
        p = __half22float2(*reinterpret_cast<__half2*>(&v1.x));
        q = __half22float2(*reinterpret_cast<__half2*>(&v1.y));
        acc.x += w1 * p.x; acc.y += w1 * p.y; acc.z += w1 * q.x; acc.w += w1 * q.y;
        p = __half22float2(*reinterpret_cast<__half2*>(&v2.x));
        q = __half22float2(*reinterpret_cast<__half2*>(&v2.y));
        acc.x += w2 * p.x; acc.y += w2 * p.y; acc.z += w2 * q.x; acc.w += w2 * q.y;
        p = __half22float2(*reinterpret_cast<__half2*>(&v3.x));
        q = __half22float2(*reinterpret_cast<__half2*>(&v3.y));
        acc.x += w3 * p.x; acc.y += w3 * p.y; acc.z += w3 * q.x; acc.w += w3 * q.y;
    }
    for (; e < e1; e++) {
        int s = g_sorted[e];
        float as = g_asrc[s * 8 + h];
        float l2 = as + adst;
        float w2 = __expf(l2 > 0.f ? l2 : 0.2f * l2);
        uint2 uv = *(const uint2*)&g_xh_h[s * 128 + lane * 4];
        float2 v0 = __half22float2(*reinterpret_cast<__half2*>(&uv.x));
        float2 v1 = __half22float2(*reinterpret_cast<__half2*>(&uv.y));
        denom += w2;
        acc.x += w2 * v0.x; acc.y += w2 * v0.y;
        acc.z += w2 * v1.x; acc.w += w2 * v1.y;
    }
    float inv = 1.f / denom;
    float4 bv = *(const float4*)&bias[lane * 4];
    float4 o;
    o.x = acc.x * inv + bv.x;
    o.y = acc.y * inv + bv.y;
    o.z = acc.z * inv + bv.z;
    o.w = acc.w * inv + bv.w;
    *(float4*)&out[warp * 128 + lane * 4] = o;
}

// ---------------------------------------------------------------------------
extern "C" void kernel_launch(void* const* d_in, const int* in_sizes, int n_in,
                              void* d_out, int out_size)
{
    const float* x    = (const float*)d_in[0];
    const int*   ei   = (const int*)d_in[1];
    const float* W    = (const float*)d_in[2];
    const float* bp   = (const float*)d_in[3];
    const float* as_  = (const float*)d_in[4];
    const float* ad_  = (const float*)d_in[5];
    const float* bias = (const float*)d_in[6];
    float* out = (float*)d_out;

    const int n  = in_sizes[0] / 128;
    const int ne = in_sizes[1] / 2;
    const int nb = (n + 1023) / 1024;

    // one-time host-side infra (no device memory involved)
    static cudaStream_t s2 = nullptr;
    static cudaEvent_t evF = nullptr, evJ = nullptr;
    if (s2 == nullptr) {
        if (cudaStreamCreateWithFlags(&s2, cudaStreamNonBlocking) != cudaSuccess)
            s2 = nullptr;
        cudaEventCreateWithFlags(&evF, cudaEventDisableTiming);
        cudaEventCreateWithFlags(&evJ, cudaEventDisableTiming);
    }

    const bool fork = (s2 != nullptr);

    if (fork) {
        // fork: gemm branch runs concurrently with CSR build
        cudaEventRecord(evF, 0);
        cudaStreamWaitEvent(s2, evF, 0);
        gemm_kernel<<<(n + 127) / 128, 256, 0, s2>>>(x, W, bp, as_, ad_, n);
        cudaEventRecord(evJ, s2);
    } else {
        gemm_kernel<<<(n + 127) / 128, 256>>>(x, W, bp, as_, ad_, n);
    }

    // CSR build branch (main stream)
    zero_kernel<<<(n + 255) / 256, 256>>>(n);
    if ((ne & 3) == 0) {
        hist4_kernel<<<(ne / 4 + 255) / 256, 256>>>(ei, ne);
    } else {
        hist_kernel<<<(ne + 255) / 256, 256>>>(ei, ne);
    }
    scan_a<<<nb, 1024>>>(n);
    scan_c<<<nb, 1024>>>(n);
    if ((ne & 3) == 0) {
        scat4_kernel<<<(ne / 4 + 255) / 256, 256>>>(ei, ne);
    } else {
        scat_kernel<<<(ne + 255) / 256, 256>>>(ei, ne);
    }

    if (fork) cudaStreamWaitEvent(0, evJ, 0);
    agg_kernel<<<(n + 7) / 8, 256>>>(bias, out, n);
}

// round 14
// speedup vs baseline: 1.3255x; 1.3255x over previous
#include <cuda_runtime.h>
#include <cuda_fp16.h>
#include <cuda_bf16.h>

#define NMAX 100000
#define EMAX 1600000

// ---- device scratch (no allocations allowed) ----
static __device__ __half g_xh_h[NMAX * 128];   // projected features fp16 [N,128]
static __device__ float g_asrc[NMAX * 8];      // per-node src logits [N,H]
static __device__ float g_adst[NMAX * 8];      // per-node dst logits [N,H]
static __device__ int   g_cnt[NMAX];           // in-degree histogram
static __device__ int   g_off[NMAX + 1];       // CSR offsets
static __device__ volatile int g_blk[128];     // scan totals+1 (0 = not ready)
static __device__ int   g_rank[EMAX];          // edge rank within dst segment
static __device__ int   g_sorted[EMAX];        // src ids grouped by dst

// ---------------------------------------------------------------------------
__global__ void zero_kernel(int n) {
    int i = blockIdx.x * blockDim.x + threadIdx.x;
    if (i < n) g_cnt[i] = 0;
    if (i < 128) g_blk[i] = 0;
}

// ---------------------------------------------------------------------------
__device__ __forceinline__ unsigned f2tf32(float f) {
    unsigned r;
    asm("cvt.rna.tf32.f32 %0, %1;" : "=r"(r) : "f"(f));
    return r;
}
__device__ __forceinline__ void mma_tf32(float* c,
    unsigned a0, unsigned a1, unsigned a2, unsigned a3,
    unsigned b0, unsigned b1)
{
    asm volatile(
        "mma.sync.aligned.m16n8k8.row.col.f32.tf32.tf32.f32 "
        "{%0,%1,%2,%3}, {%4,%5,%6,%7}, {%8,%9}, {%0,%1,%2,%3};"
        : "+f"(c[0]), "+f"(c[1]), "+f"(c[2]), "+f"(c[3])
        : "r"(a0), "r"(a1), "r"(a2), "r"(a3), "r"(b0), "r"(b1));
}

// xh = x @ W^T + b via tf32 mma; att logits fused into the epilogue.
__global__ __launch_bounds__(256, 2) void gemm_kernel(
    const float* __restrict__ x, const float* __restrict__ W,
    const float* __restrict__ b,
    const float* __restrict__ att_s, const float* __restrict__ att_d, int n)
{
    __shared__ unsigned ws[128 * 36];   // W[j][k] chunk, tf32 bits
    __shared__ unsigned xs[128 * 36];   // x[r][k] chunk, tf32 bits
    __shared__ float as_sm[128], ad_sm[128], b_sm[128];
    const int tid = threadIdx.x;
    const int lane = tid & 31, warp = tid >> 5;
    const int row0 = blockIdx.x * 128;
    const int g = lane >> 2;        // groupID (row selector)
    const int tg = lane & 3;        // thread-in-group (col selector)

    if (tid < 128) {
        as_sm[tid] = att_s[tid];
        ad_sm[tid] = att_d[tid];
        b_sm[tid]  = b[tid];
    }

    float acc[16][4];
#pragma unroll
    for (int t = 0; t < 16; t++)
#pragma unroll
        for (int c = 0; c < 4; c++) acc[t][c] = 0.f;

    for (int kk = 0; kk < 128; kk += 32) {
#pragma unroll
        for (int i = 0; i < 4; i++) {           // W chunk: 128x32
            int id = tid + i * 256;             // float4 index
            int j = id >> 3, kq = (id & 7) * 4;
            float4 v = *(const float4*)&W[j * 128 + kk + kq];
            unsigned* d = &ws[j * 36 + kq];
            d[0] = f2tf32(v.x); d[1] = f2tf32(v.y);
            d[2] = f2tf32(v.z); d[3] = f2tf32(v.w);
        }
#pragma unroll
        for (int i = 0; i < 4; i++) {           // x chunk: 128x32
            int id = tid + i * 256;
            int r = id >> 3, kq = (id & 7) * 4;
            int row = row0 + r;
            float4 v = (row < n) ? *(const float4*)&x[row * 128 + kk + kq]
                                 : make_float4(0.f, 0.f, 0.f, 0.f);
            unsigned* d = &xs[r * 36 + kq];
            d[0] = f2tf32(v.x); d[1] = f2tf32(v.y);
            d[2] = f2tf32(v.z); d[3] = f2tf32(v.w);
        }
        __syncthreads();
        const int rA = warp * 16 + g;
#pragma unroll
        for (int ks = 0; ks < 32; ks += 8) {
            unsigned a0 = xs[rA * 36 + ks + tg];
            unsigned a1 = xs[(rA + 8) * 36 + ks + tg];
            unsigned a2 = xs[rA * 36 + ks + 4 + tg];
            unsigned a3 = xs[(rA + 8) * 36 + ks + 4 + tg];
#pragma unroll
            for (int t = 0; t < 16; t++) {
                int jn = t * 8 + g;
                unsigned b0 = ws[jn * 36 + ks + tg];
                unsigned b1 = ws[jn * 36 + ks + 4 + tg];
                mma_tf32(acc[t], a0, a1, a2, a3, b0, b1);
            }
        }
        __syncthreads();
    }

    // epilogue: +bias, store fp16, fused per-head attention logits
    const int r0 = row0 + warp * 16 + g;
    const bool okA = (r0 < n), okB = (r0 + 8 < n);
#pragma unroll
    for (int h = 0; h < 8; h++) {
        float sA = 0.f, dA = 0.f, sB = 0.f, dB = 0.f;
#pragma unroll
        for (int tt = 0; tt < 2; tt++) {
            const int t  = 2 * h + tt;
            const int j0 = t * 8 + 2 * tg;
            float bx = b_sm[j0], by = b_sm[j0 + 1];
            float v00 = acc[t][0] + bx, v01 = acc[t][1] + by;
            float v10 = acc[t][2] + bx, v11 = acc[t][3] + by;
            if (okA) *(__half2*)&g_xh_h[r0 * 128 + j0] = __floats2half2_rn(v00, v01);
            if (okB) *(__half2*)&g_xh_h[(r0 + 8) * 128 + j0] = __floats2half2_rn(v10, v11);
            float a0 = as_sm[j0], a1 = as_sm[j0 + 1];
            float q0 = ad_sm[j0], q1 = ad_sm[j0 + 1];
            sA += v00 * a0 + v01 * a1;  dA += v00 * q0 + v01 * q1;
            sB += v10 * a0 + v11 * a1;  dB += v10 * q0 + v11 * q1;
        }
        sA += __shfl_xor_sync(0xffffffffu, sA, 1); sA += __shfl_xor_sync(0xffffffffu, sA, 2);
        dA += __shfl_xor_sync(0xffffffffu, dA, 1); dA += __shfl_xor_sync(0xffffffffu, dA, 2);
        sB += __shfl_xor_sync(0xffffffffu, sB, 1); sB += __shfl_xor_sync(0xffffffffu, sB, 2);
        dB += __shfl_xor_sync(0xffffffffu, dB, 1); dB += __shfl_xor_sync(0xffffffffu, dB, 2);
        if ((h & 3) == tg) {
            if (okA) { g_asrc[r0 * 8 + h] = sA; g_adst[r0 * 8 + h] = dA; }
            if (okB) { g_asrc[(r0 + 8) * 8 + h] = sB; g_adst[(r0 + 8) * 8 + h] = dB; }
        }
    }
}

// ---------------------------------------------------------------------------
// histogram + per-edge rank within destination segment
__global__ void hist4_kernel(const int* __restrict__ ei, int ne) {
    int i = blockIdx.x * blockDim.x + threadIdx.x;
    int ne4 = ne >> 2;
    if (i < ne4) {
        int4 d = ((const int4*)(ei + ne))[i];
        int4 r;
        r.x = atomicAdd(&g_cnt[d.x], 1);
        r.y = atomicAdd(&g_cnt[d.y], 1);
        r.z = atomicAdd(&g_cnt[d.z], 1);
        r.w = atomicAdd(&g_cnt[d.w], 1);
        ((int4*)g_rank)[i] = r;
    }
}
__global__ void hist_kernel(const int* __restrict__ ei, int ne) {
    int i = blockIdx.x * blockDim.x + threadIdx.x;
    if (i < ne) g_rank[i] = atomicAdd(&g_cnt[ei[ne + i]], 1);
}

// ---------------------------------------------------------------------------
// Fused exclusive scan over g_cnt: single kernel, decoupled lookback.
// <=128 blocks, all resident simultaneously (grid <= #SMs) => spin is safe.
// Block publishes (total+1) to g_blk[b] (0 = not ready), then sums
// predecessors' totals while doing its local scan.
__global__ void scan_k(int n) {
    __shared__ int wsum[32];
    __shared__ int blockoff;
    const int t = threadIdx.x;
    const int idx = blockIdx.x * 1024 + t;
    const int lane = t & 31, w = t >> 5;
    const int v = (idx < n) ? g_cnt[idx] : 0;

    // local inclusive scan within warp
    int inc = v;
#pragma unroll
    for (int d = 1; d < 32; d <<= 1) {
        int u = __shfl_up_sync(0xffffffffu, inc, d);
        if (lane >= d) inc += u;
    }
    if (lane == 31) wsum[w] = inc;
    __syncthreads();

    // warp 0: scan warp totals, publish block total, lookback
    if (w == 0) {
        int s = wsum[lane];
        int si = s;
#pragma unroll
        for (int d = 1; d < 32; d <<= 1) {
            int u = __shfl_up_sync(0xffffffffu, si, d);
            if (lane >= d) si += u;
        }
        if (lane == 31) {
            __threadfence();
            g_blk[blockIdx.x] = si + 1;        // publish total (+1 ready flag)
        }
        wsum[lane] = si - s;                   // exclusive warp offsets
        // lookback: sum totals of preceding blocks (lane-strided spin)
        int acc = 0;
        for (int j = lane; j < blockIdx.x; j += 32) {
            int bv;
            do { bv = g_blk[j]; } while (bv == 0);
            acc += bv - 1;
        }
#pragma unroll
        for (int d = 16; d; d >>= 1) acc += __shfl_xor_sync(0xffffffffu, acc, d);
        if (lane == 0) blockoff = acc;
    }
    __syncthreads();

    int excl = (inc - v) + wsum[w] + blockoff;
    if (idx < n) g_off[idx] = excl;
    if (idx == n - 1) g_off[n] = excl + v;
}

// ---------------------------------------------------------------------------
// atomic-free scatter using precomputed ranks
__global__ void scat4_kernel(const int* __restrict__ ei, int ne) {
    int i = blockIdx.x * blockDim.x + threadIdx.x;
    int ne4 = ne >> 2;
    if (i < ne4) {
        int4 s = ((const int4*)ei)[i];
        int4 d = ((const int4*)(ei + ne))[i];
        int4 r = ((const int4*)g_rank)[i];
        g_sorted[g_off[d.x] + r.x] = s.x;
        g_sorted[g_off[d.y] + r.y] = s.y;
        g_sorted[g_off[d.z] + r.z] = s.z;
        g_sorted[g_off[d.w] + r.w] = s.w;
    }
}
__global__ void scat_kernel(const int* __restrict__ ei, int ne) {
    int i = blockIdx.x * blockDim.x + threadIdx.x;
    if (i < ne) {
        int d = ei[ne + i];
        g_sorted[g_off[d] + g_rank[i]] = ei[i];
    }
}

// ---------------------------------------------------------------------------
// Warp per destination node. Lane l owns dims [4l,4l+4) => head = l>>2.
// Softmax without max-subtraction (logits bounded):
//   out = (sum_e w_e * xh[src_e]) / (sum_e w_e),  w = exp(leakyrelu(asrc+adst))
__global__ void agg_kernel(const float* __restrict__ bias,
                           float* __restrict__ out, int n)
{
    int warp = (blockIdx.x * blockDim.x + threadIdx.x) >> 5;
    int lane = threadIdx.x & 31;
    if (warp >= n) return;
    int h = lane >> 2;
    float adst = g_adst[warp * 8 + h];

    // self loop
    float asl = g_asrc[warp * 8 + h];
    float lg = asl + adst;
    float wgt = __expf(lg > 0.f ? lg : 0.2f * lg);
    uint2 u = *(const uint2*)&g_xh_h[warp * 128 + lane * 4];
    float2 f0 = __half22float2(*reinterpret_cast<__half2*>(&u.x));
    float2 f1 = __half22float2(*reinterpret_cast<__half2*>(&u.y));
    float denom = wgt;
    float4 acc;
    acc.x = wgt * f0.x; acc.y = wgt * f0.y;
    acc.z = wgt * f1.x; acc.w = wgt * f1.y;

    const int e1 = g_off[warp + 1];
    int e = g_off[warp];
    for (; e + 3 < e1; e += 4) {
        int s0 = g_sorted[e],     s1 = g_sorted[e + 1];
        int s2 = g_sorted[e + 2], s3 = g_sorted[e + 3];
        float a0 = g_asrc[s0 * 8 + h], a1 = g_asrc[s1 * 8 + h];
        float a2 = g_asrc[s2 * 8 + h], a3 = g_asrc[s3 * 8 + h];
        uint2 v0 = *(const uint2*)&g_xh_h[s0 * 128 + lane * 4];
        uint2 v1 = *(const uint2*)&g_xh_h[s1 * 128 + lane * 4];
        uint2 v2 = *(const uint2*)&g_xh_h[s2 * 128 + lane * 4];
        uint2 v3 = *(const uint2*)&g_xh_h[s3 * 128 + lane * 4];
        float l0 = a0 + adst, l1 = a1 + adst, l2 = a2 + adst, l3 = a3 + adst;
        float w0 = __expf(l0 > 0.f ? l0 : 0.2f * l0);
        float w1 = __expf(l1 > 0.f ? l1 : 0.2f * l1);
        float w2 = __expf(l2 > 0.f ? l2 : 0.2f * l2);
        float w3 = __expf(l3 > 0.f ? l3 : 0.2f * l3);
        denom += w0 + w1 + w2 + w3;
        float2 p, q;
        p = __half22float2(*reinterpret_cast<__half2*>(&v0.x));
        q = __half22float2(*reinterpret_cast<__half2*>(&v0.y));
        acc.x += w0 * p.x; acc.y += w0 * p.y; acc.z += w0 * q.x; acc.w += w0 * q.y;
        p = __half22float2(*reinterpret_cast<__half2*>(&v1.x));
        q = __half22float2(*reinterpret_cast<__half2*>(&v1.y));
        acc.x += w1 * p.x; acc.y += w1 * p.y; acc.z += w1 * q.x; acc.w += w1 * q.y;
        p = __half22float2(*reinterpret_cast<__half2*>(&v2.x));
        q = __half22float2(*reinterpret_cast<__half2*>(&v2.y));
        acc.x += w2 * p.x; acc.y += w2 * p.y; acc.z += w2 * q.x; acc.w += w2 * q.y;
        p = __half22float2(*reinterpret_cast<__half2*>(&v3.x));
        q = __half22float2(*reinterpret_cast<__half2*>(&v3.y));
        acc.x += w3 * p.x; acc.y += w3 * p.y; acc.z += w3 * q.x; acc.w += w3 * q.y;
    }
    for (; e < e1; e++) {
        int s = g_sorted[e];
        float as = g_asrc[s * 8 + h];
        float l2 = as + adst;
        float w2 = __expf(l2 > 0.f ? l2 : 0.2f * l2);
        uint2 uv = *(const uint2*)&g_xh_h[s * 128 + lane * 4];
        float2 v0 = __half22float2(*reinterpret_cast<__half2*>(&uv.x));
        float2 v1 = __half22float2(*reinterpret_cast<__half2*>(&uv.y));
        denom += w2;
        acc.x += w2 * v0.x; acc.y += w2 * v0.y;
        acc.z += w2 * v1.x; acc.w += w2 * v1.y;
    }
    float inv = 1.f / denom;
    float4 bv = *(const float4*)&bias[lane * 4];
    float4 o;
    o.x = acc.x * inv + bv.x;
    o.y = acc.y * inv + bv.y;
    o.z = acc.z * inv + bv.z;
    o.w = acc.w * inv + bv.w;
    *(float4*)&out[warp * 128 + lane * 4] = o;
}

// ---------------------------------------------------------------------------
extern "C" void kernel_launch(void* const* d_in, const int* in_sizes, int n_in,
                              void* d_out, int out_size)
{
    const float* x    = (const float*)d_in[0];
    const int*   ei   = (const int*)d_in[1];
    const float* W    = (const float*)d_in[2];
    const float* bp   = (const float*)d_in[3];
    const float* as_  = (const float*)d_in[4];
    const float* ad_  = (const float*)d_in[5];
    const float* bias = (const float*)d_in[6];
    float* out = (float*)d_out;

    const int n  = in_sizes[0] / 128;
    const int ne = in_sizes[1] / 2;
    const int nb = (n + 1023) / 1024;   // <= 128 required by scan_k

    zero_kernel<<<(n + 255) / 256, 256>>>(n);
    gemm_kernel<<<(n + 127) / 128, 256>>>(x, W, bp, as_, ad_, n);
    if ((ne & 3) == 0) {
        hist4_kernel<<<(ne / 4 + 255) / 256, 256>>>(ei, ne);
    } else {
        hist_kernel<<<(ne + 255) / 256, 256>>>(ei, ne);
    }
    scan_k<<<nb, 1024>>>(n);
    if ((ne & 3) == 0) {
        scat4_kernel<<<(ne / 4 + 255) / 256, 256>>>(ei, ne);
    } else {
        scat_kernel<<<(ne + 255) / 256, 256>>>(ei, ne);
    }
    agg_kernel<<<(n + 7) / 8, 256>>>(bias, out, n);
}